// round 7
// baseline (speedup 1.0000x reference)
#include <cuda_runtime.h>
#include <cstdint>
#include <cstddef>

// Problem sizes
#define BB 64
#define TT 2048
#define DD 512

// Recurrence config
#define NCTA 128
#define RTHREADS 256
// SMEM: Hs [512][64] f32 (128KB) + fused weight splat [4][512] ulonglong2 (32KB)
//       + reduction scratch 4*32*2 ull (2KB)
#define RSMEM (512*64*4 + 4*512*16 + 4*32*2*8)

// -------- device scratch (no allocs allowed) --------
__device__ float g_Xg[(size_t)TT * BB * DD];   // [t][b][n], includes bias
__device__ float g_Xc[(size_t)TT * BB * DD];
__device__ float g_H[2][DD * BB];              // [n][b] layout, double buffered
__device__ unsigned g_bar;                     // monotonic barrier counter (reset in-kernel)

// ==================== Phase 1: x-projection GEMM ====================
// C[r, n] = seq[r, :] @ W[512: , n] + bias[n],  r = b*T + t, stored to X[t][b][n]
// Tiles: BM=128, BN=128, BK=8, 256 threads, 8x8 per thread.
__global__ __launch_bounds__(256) void xproj_kernel(
    const float* __restrict__ seq, const float* __restrict__ Wg,
    const float* __restrict__ bgate, const float* __restrict__ Wc,
    const float* __restrict__ bcand)
{
    __shared__ float As[8 * 132];
    __shared__ float Bs[8 * 132];

    const int bm = blockIdx.x;            // 0..1023
    const int bn = blockIdx.y;            // 0..7 ; 0-3 gate, 4-7 cand
    const bool isCand = bn >= 4;
    const float* __restrict__ W    = isCand ? Wc : Wg;
    const float* __restrict__ bias = isCand ? bcand : bgate;
    float* __restrict__ Xout       = isCand ? g_Xc : g_Xg;
    const int n0 = (bn & 3) * 128;
    const int m0 = bm * 128;

    const int tid  = threadIdx.x;
    const int arow = tid >> 1;            // 0..127
    const int akk  = (tid & 1) * 4;       // 0 or 4
    const int brow = tid >> 5;            // 0..7
    const int bcol = (tid & 31) * 4;      // 0..124
    const int trow = tid >> 4;            // 0..15
    const int tcol = tid & 15;            // 0..15

    float acc[8][8];
#pragma unroll
    for (int i = 0; i < 8; i++)
#pragma unroll
        for (int j = 0; j < 8; j++) acc[i][j] = 0.0f;

    for (int k0 = 0; k0 < 512; k0 += 8) {
        float4 av = *(const float4*)(seq + (size_t)(m0 + arow) * 512 + k0 + akk);
        As[(akk + 0) * 132 + arow] = av.x;
        As[(akk + 1) * 132 + arow] = av.y;
        As[(akk + 2) * 132 + arow] = av.z;
        As[(akk + 3) * 132 + arow] = av.w;
        float4 bv = *(const float4*)(W + (size_t)(512 + k0 + brow) * 512 + n0 + bcol);
        *(float4*)(Bs + brow * 132 + bcol) = bv;
        __syncthreads();
#pragma unroll
        for (int k = 0; k < 8; k++) {
            float4 a0 = *(const float4*)(As + k * 132 + trow * 8);
            float4 a1 = *(const float4*)(As + k * 132 + trow * 8 + 4);
            float4 b0 = *(const float4*)(Bs + k * 132 + tcol * 8);
            float4 b1 = *(const float4*)(Bs + k * 132 + tcol * 8 + 4);
            float a[8] = {a0.x, a0.y, a0.z, a0.w, a1.x, a1.y, a1.z, a1.w};
            float b[8] = {b0.x, b0.y, b0.z, b0.w, b1.x, b1.y, b1.z, b1.w};
#pragma unroll
            for (int i = 0; i < 8; i++)
#pragma unroll
                for (int j = 0; j < 8; j++) acc[i][j] = fmaf(a[i], b[j], acc[i][j]);
        }
        __syncthreads();
    }

    float bb0[8];
#pragma unroll
    for (int j = 0; j < 8; j++) bb0[j] = bias[n0 + tcol * 8 + j];

#pragma unroll
    for (int i = 0; i < 8; i++) {
        int r  = m0 + trow * 8 + i;
        int bb = r >> 11;        // batch
        int tt = r & 2047;       // time
        float* orow = Xout + ((size_t)tt * 64 + bb) * 512 + n0 + tcol * 8;
        float4 o0 = make_float4(acc[i][0] + bb0[0], acc[i][1] + bb0[1],
                                acc[i][2] + bb0[2], acc[i][3] + bb0[3]);
        float4 o1 = make_float4(acc[i][4] + bb0[4], acc[i][5] + bb0[5],
                                acc[i][6] + bb0[6], acc[i][7] + bb0[7]);
        *(float4*)(orow)     = o0;
        *(float4*)(orow + 4) = o1;
    }
}

// ==================== Phase 2: persistent recurrence ====================

__device__ __forceinline__ unsigned ld_acq(const unsigned* p) {
    unsigned v;
    asm volatile("ld.global.acquire.gpu.u32 %0, [%1];" : "=r"(v) : "l"(p) : "memory");
    return v;
}

__device__ __forceinline__ void grid_barrier(unsigned target) {
    __syncthreads();
    if (threadIdx.x == 0) {
        __threadfence();
        atomicAdd(&g_bar, 1u);
        while (ld_acq(&g_bar) < target) { }   // hot path: tight acquire spin
    }
    __syncthreads();
}

__global__ void __launch_bounds__(RTHREADS, 1) recur_kernel(
    const float* __restrict__ Wg, const float* __restrict__ Wc,
    float* __restrict__ out)
{
    extern __shared__ float smem[];
    float*              Hs  = smem;                             // [n=512][b=64]
    ulonglong2*         Wb  = (ulonglong2*)(smem + 512 * 64);   // [jp=4][k=512]: {wg2, wc2}
    unsigned long long* Red = (unsigned long long*)(Wb + 4 * 512); // [jp=4][bp=32][2]

    const int tid   = threadIdx.x;       // 0..255
    const int cta   = blockIdx.x;
    const int nbase = cta * 4;

    // Load this CTA's weight columns once, splatted+fused for f32x2 FMA.
    for (int idx = tid; idx < 4 * 512; idx += RTHREADS) {
        int jp = idx & 3, k = idx >> 2;
        float wg = Wg[(size_t)k * 512 + nbase + jp];   // h-part: rows 0..511
        float wc = Wc[(size_t)k * 512 + nbase + jp];
        unsigned gbits = __float_as_uint(wg);
        unsigned cbits = __float_as_uint(wc);
        ulonglong2 v;
        v.x = ((unsigned long long)gbits << 32) | gbits;
        v.y = ((unsigned long long)cbits << 32) | cbits;
        Wb[jp * 512 + k] = v;
    }

    // Zero H buffer 0 (h0 = 0). 32768 floats / 128 CTAs = 256 each.
    g_H[0][cta * 256 + tid] = 0.0f;

    unsigned target = gridDim.x;
    grid_barrier(target);
    target += gridDim.x;

    const int bp    = tid & 31;
    const int wid   = tid >> 5;          // 0..7
    const int jp    = wid & 3;           // column 0..3
    const int khalf = wid >> 2;          // 0: k<256, 1: k>=256
    const int kbase = khalf * 256;
    const int b0 = bp * 2, b1 = b0 + 1;
    const int n  = nbase + jp;

    const ulonglong2* __restrict__ wbp = Wb + jp * 512 + kbase;
    unsigned long long* __restrict__ red = Red + (jp * 32 + bp) * 2;

    for (int t = 0; t < TT; t++) {
        // Prefetch per-step x-projections (lower half only; independent of H).
        float xg0 = 0.f, xg1 = 0.f, xc0 = 0.f, xc1 = 0.f;
        if (khalf == 0) {
            const size_t xoff = (size_t)t * 64 * 512;
            xg0 = g_Xg[xoff + (size_t)b0 * 512 + n];
            xg1 = g_Xg[xoff + (size_t)b1 * 512 + n];
            xc0 = g_Xc[xoff + (size_t)b0 * 512 + n];
            xc1 = g_Xc[xoff + (size_t)b1 * 512 + n];
        }

        // Stage full H (other CTAs wrote it) — MUST bypass L1 (.cg).
        const float4* Hg4 = (const float4*)g_H[t & 1];
        float4* Hs4 = (float4*)Hs;
#pragma unroll 8
        for (int f = tid; f < 8192; f += RTHREADS) {
            Hs4[f] = __ldcg(Hg4 + f);
        }
        __syncthreads();

        // Packed f32x2 partial dot over this warp's K half (256 iters).
        unsigned long long accg = 0ull, accc = 0ull;
        const unsigned long long* H2 = (const unsigned long long*)Hs + kbase * 32;
#pragma unroll 8
        for (int k = 0; k < 256; k++) {
            unsigned long long h2 = H2[k * 32 + bp];
            ulonglong2 w = wbp[k];      // LDS.128 broadcast: {wg2, wc2}
            asm("fma.rn.f32x2 %0, %1, %2, %0;" : "+l"(accg) : "l"(h2), "l"(w.x));
            asm("fma.rn.f32x2 %0, %1, %2, %0;" : "+l"(accc) : "l"(h2), "l"(w.y));
        }

        // Upper half deposits partials; lower half combines + epilogue.
        if (khalf == 1) {
            red[0] = accg;
            red[1] = accc;
        }
        __syncthreads();

        if (khalf == 0) {
            unsigned long long pg = red[0], pc = red[1];
            asm("add.rn.f32x2 %0, %0, %1;" : "+l"(accg) : "l"(pg));
            asm("add.rn.f32x2 %0, %0, %1;" : "+l"(accc) : "l"(pc));

            // h_old for this thread's column.
            float h0 = Hs[n * 64 + b0];
            float h1 = Hs[n * 64 + b1];

            float ag0 = __uint_as_float((unsigned)(accg));
            float ag1 = __uint_as_float((unsigned)(accg >> 32));
            float ac0 = __uint_as_float((unsigned)(accc));
            float ac1 = __uint_as_float((unsigned)(accc >> 32));

            float pg0 = ag0 + xg0, pg1 = ag1 + xg1;
            float pc0 = ac0 + xc0, pc1 = ac1 + xc1;

            float gg0 = 1.0f / (1.0f + __expf(-pg0));
            float gg1 = 1.0f / (1.0f + __expf(-pg1));
            float cc0 = tanhf(pc0);
            float cc1 = tanhf(pc1);

            float hn0 = cc0 + gg0 * (h0 - cc0);   // g*h + (1-g)*c
            float hn1 = cc1 + gg1 * (h1 - cc1);

            float* Hn = g_H[(t + 1) & 1];
            *(float2*)(Hn + n * 64 + b0) = make_float2(hn0, hn1);

            if (t == TT - 1) {
                out[(size_t)b0 * 512 + n] = hn0;
                out[(size_t)b1 * 512 + n] = hn1;
            }
        }

        grid_barrier(target);
        target += gridDim.x;
    }

    // Final handshake: reset g_bar for the next graph replay.
    __syncthreads();
    if (tid == 0) {
        __threadfence();
        atomicAdd(&g_bar, 1u);
        if (cta == 0) {
            while (ld_acq(&g_bar) < target) { __nanosleep(64); }  // cold path
            asm volatile("st.global.u32 [%0], %1;" :: "l"(&g_bar), "r"(0u) : "memory");
        }
    }
}

// ==================== launch ====================
extern "C" void kernel_launch(void* const* d_in, const int* in_sizes, int n_in,
                              void* d_out, int out_size)
{
    const float* seq = (const float*)d_in[0];
    const float* Wg  = (const float*)d_in[1];
    const float* bg  = (const float*)d_in[2];
    const float* Wc  = (const float*)d_in[3];
    const float* bc  = (const float*)d_in[4];
    float* out = (float*)d_out;

    dim3 g1(1024, 8);
    xproj_kernel<<<g1, 256>>>(seq, Wg, bg, Wc, bc);

    cudaFuncSetAttribute(recur_kernel, cudaFuncAttributeMaxDynamicSharedMemorySize, RSMEM);
    recur_kernel<<<NCTA, RTHREADS, RSMEM>>>(Wg, Wc, out);
}